// round 7
// baseline (speedup 1.0000x reference)
#include <cuda_runtime.h>
#include <math.h>

#define N_NODES 100000
#define N_EDGES 1600000
#define IN_DIM  64
#define EMB     128
#define ED      32

#define SCAN_BLK 512
#define NBLK ((N_NODES + SCAN_BLK - 1) / SCAN_BLK)   // 196

__device__ float g_agg[2][(size_t)N_NODES * IN_DIM];
__device__ float g_t[2][(size_t)N_NODES * EMB];

// CSR scratch
__device__ int g_deg[2][N_NODES];
__device__ int g_cur[2][N_NODES];
__device__ int g_off[2][N_NODES + 1];
__device__ int g_partial[2][NBLK];
__device__ int g_pscan[2][NBLK];
__device__ int g_elist[2][N_EDGES];

// ---------------------------------------------------------------------------
// CSR build
// ---------------------------------------------------------------------------
__global__ void zero_deg_kernel() {
    int i = blockIdx.x * blockDim.x + threadIdx.x;
    if (i < N_NODES) { g_deg[0][i] = 0; g_deg[1][i] = 0; }
}

__global__ void count_kernel(const int* __restrict__ ei) {
    int e = blockIdx.x * blockDim.x + threadIdx.x;
    if (e < N_EDGES) {
        int s = ei[e];
        int d = ei[N_EDGES + e];
        atomicAdd(&g_deg[0][d], 1);   // conv_in aggregates at dst
        atomicAdd(&g_deg[1][s], 1);   // conv_out aggregates at src
    }
}

__global__ void scan1_kernel() {   // grid (NBLK, 2), 512 thr: block sums
    const int dir = blockIdx.y;
    __shared__ int sred[SCAN_BLK];
    int i = blockIdx.x * SCAN_BLK + threadIdx.x;
    sred[threadIdx.x] = (i < N_NODES) ? g_deg[dir][i] : 0;
    __syncthreads();
    for (int ofs = SCAN_BLK / 2; ofs > 0; ofs >>= 1) {
        if (threadIdx.x < ofs) sred[threadIdx.x] += sred[threadIdx.x + ofs];
        __syncthreads();
    }
    if (threadIdx.x == 0) g_partial[dir][blockIdx.x] = sred[0];
}

__global__ void scan2_kernel() {   // grid (1, 2), 256 thr: scan partials
    const int dir = blockIdx.y;
    __shared__ int sb[2][256];
    int t = threadIdx.x;
    int v = (t < NBLK) ? g_partial[dir][t] : 0;
    sb[0][t] = v;
    __syncthreads();
    int cur = 0;
#pragma unroll
    for (int ofs = 1; ofs < 256; ofs <<= 1) {
        int val = sb[cur][t];
        if (t >= ofs) val += sb[cur][t - ofs];
        sb[cur ^ 1][t] = val;
        __syncthreads();
        cur ^= 1;
    }
    if (t < NBLK) g_pscan[dir][t] = sb[cur][t] - v;   // exclusive
}

__global__ void scan3_kernel() {   // grid (NBLK, 2), 512 thr: final offsets
    const int dir = blockIdx.y;
    __shared__ int sb[2][SCAN_BLK];
    int t = threadIdx.x;
    int i = blockIdx.x * SCAN_BLK + t;
    int v = (i < N_NODES) ? g_deg[dir][i] : 0;
    sb[0][t] = v;
    __syncthreads();
    int cur = 0;
#pragma unroll
    for (int ofs = 1; ofs < SCAN_BLK; ofs <<= 1) {
        int val = sb[cur][t];
        if (t >= ofs) val += sb[cur][t - ofs];
        sb[cur ^ 1][t] = val;
        __syncthreads();
        cur ^= 1;
    }
    int incl = sb[cur][t];
    int base = g_pscan[dir][blockIdx.x];
    if (i < N_NODES) {
        int excl = base + incl - v;
        g_off[dir][i] = excl;
        g_cur[dir][i] = excl;
        if (i == N_NODES - 1) g_off[dir][N_NODES] = base + incl;
    }
}

__global__ void fill_kernel(const int* __restrict__ ei) {
    int e = blockIdx.x * blockDim.x + threadIdx.x;
    if (e < N_EDGES) {
        int s = ei[e];
        int d = ei[N_EDGES + e];
        int p0 = atomicAdd(&g_cur[0][d], 1);
        g_elist[0][p0] = e;
        int p1 = atomicAdd(&g_cur[1][s], 1);
        g_elist[1][p1] = e;
    }
}

// ---------------------------------------------------------------------------
// Aggregation: warp per node, 4 edges in flight, register accumulation,
// single plain store per node. No fp32 atomics anywhere.
// ---------------------------------------------------------------------------
__global__ __launch_bounds__(256, 2) void agg_kernel(
    const float2* __restrict__ x2,        // x as [N_NODES][32] float2
    const int* __restrict__ ei,           // [2][N_EDGES]
    const float* __restrict__ ea,         // [N_EDGES][32]
    const float2* __restrict__ We_in2,
    const float2* __restrict__ be_in2,
    const float2* __restrict__ We_out2,
    const float2* __restrict__ be_out2)
{
    const int dir  = blockIdx.y;
    const int lane = threadIdx.x & 31;
    const int w    = threadIdx.x >> 5;

    const float2* We2 = dir ? We_out2 : We_in2;
    const float2  bias = dir ? be_out2[lane] : be_in2[lane];
    const int* gidx = dir ? (ei + N_EDGES) : ei;   // gather side
    const int* off   = g_off[dir];
    const int* elist = g_elist[dir];
    float* __restrict__ agg = g_agg[dir];

    float2 wreg[32];
#pragma unroll
    for (int k = 0; k < 32; k++) wreg[k] = We2[k * 32 + lane];

    __shared__ float sEa[8][4][32];

    const int warpGlobal = blockIdx.x * 8 + w;
    const int nwarps = gridDim.x * 8;

    for (int n = warpGlobal; n < N_NODES; n += nwarps) {
        const int beg = off[n];
        const int end = off[n + 1];
        float2 accN = make_float2(0.f, 0.f);

        for (int j0 = beg; j0 < end; j0 += 4) {
            bool hv[4];
            int  ee[4], ss[4];
#pragma unroll
            for (int i = 0; i < 4; i++) {
                hv[i] = (j0 + i < end);
                ee[i] = elist[hv[i] ? (j0 + i) : j0];
            }
#pragma unroll
            for (int i = 0; i < 4; i++) ss[i] = gidx[ee[i]];

            float2 xg[4];
#pragma unroll
            for (int i = 0; i < 4; i++)
                xg[i] = x2[(size_t)ss[i] * 32 + lane];
            float eav[4];
#pragma unroll
            for (int i = 0; i < 4; i++)
                eav[i] = ea[(size_t)ee[i] * 32 + lane];

#pragma unroll
            for (int i = 0; i < 4; i++)
                sEa[w][i][lane] = eav[i];
            __syncwarp();

            float2 m[4];
#pragma unroll
            for (int i = 0; i < 4; i++) {
                m[i].x = xg[i].x + bias.x;
                m[i].y = xg[i].y + bias.y;
            }
#pragma unroll
            for (int k = 0; k < 32; k++) {
                float a0 = sEa[w][0][k];
                float a1 = sEa[w][1][k];
                float a2 = sEa[w][2][k];
                float a3 = sEa[w][3][k];
                m[0].x = fmaf(a0, wreg[k].x, m[0].x);
                m[0].y = fmaf(a0, wreg[k].y, m[0].y);
                m[1].x = fmaf(a1, wreg[k].x, m[1].x);
                m[1].y = fmaf(a1, wreg[k].y, m[1].y);
                m[2].x = fmaf(a2, wreg[k].x, m[2].x);
                m[2].y = fmaf(a2, wreg[k].y, m[2].y);
                m[3].x = fmaf(a3, wreg[k].x, m[3].x);
                m[3].y = fmaf(a3, wreg[k].y, m[3].y);
            }
#pragma unroll
            for (int i = 0; i < 4; i++) {
                float mx = fmaxf(m[i].x, 0.f);
                float my = fmaxf(m[i].y, 0.f);
                if (hv[i]) { accN.x += mx; accN.y += my; }
            }
            __syncwarp();
        }
        *(float2*)&agg[(size_t)n * 64 + 2 * lane] = accN;
    }
}

// ---------------------------------------------------------------------------
// GEMM: 128(M) x 128(N) block tile, 256 threads, 8x8 microtile.
// ---------------------------------------------------------------------------
__device__ __forceinline__ void gemm_chunk128(
    const float* __restrict__ A, const float* __restrict__ Aadd, int lda4,
    const float* __restrict__ W, int k0, int m0, float scale,
    float (*sA)[36], float (*sW)[128], float acc[8][8], int tid)
{
    const float4* A4  = (const float4*)A;
    const float4* Aa4 = (const float4*)Aadd;
#pragma unroll
    for (int it = 0; it < 4; ++it) {
        int idx = it * 256 + tid;
        int r   = idx >> 3;
        int cq  = idx & 7;
        float4 v = make_float4(0.f, 0.f, 0.f, 0.f);
        int gr = m0 + r;
        if (gr < N_NODES) {
            v = A4[(size_t)gr * lda4 + (k0 >> 2) + cq];
            if (Aadd) {
                float4 u = Aa4[(size_t)gr * lda4 + (k0 >> 2) + cq];
                v.x += u.x; v.y += u.y; v.z += u.z; v.w += u.w;
            }
            v.x *= scale; v.y *= scale; v.z *= scale; v.w *= scale;
        }
        *(float4*)&sA[r][cq * 4] = v;
    }
    const float4* W4 = (const float4*)W;
#pragma unroll
    for (int it = 0; it < 4; ++it) {
        int idx = it * 256 + tid;
        int kr  = idx >> 5;
        int cq  = idx & 31;
        *(float4*)&sW[kr][cq * 4] = W4[(size_t)(k0 + kr) * 32 + cq];
    }
    __syncthreads();

    const int rg = (tid >> 4) * 8;
    const int cg = (tid & 15) * 8;
#pragma unroll
    for (int k = 0; k < 32; k++) {
        float av[8];
#pragma unroll
        for (int i = 0; i < 8; i++) av[i] = sA[rg + i][k];
        float bv[8];
        *(float4*)&bv[0] = *(const float4*)&sW[k][cg];
        *(float4*)&bv[4] = *(const float4*)&sW[k][cg + 4];
#pragma unroll
        for (int i = 0; i < 8; i++)
#pragma unroll
            for (int j = 0; j < 8; j++)
                acc[i][j] = fmaf(av[i], bv[j], acc[i][j]);
    }
    __syncthreads();
}

__device__ __forceinline__ float gelu_exact(float v) {
    return 0.5f * v * (1.f + erff(v * 0.70710678118654752f));
}

// ---------------------------------------------------------------------------
// N1: t[dir] = gelu((x + agg[dir]) @ W1 + b1)
// ---------------------------------------------------------------------------
__global__ __launch_bounds__(256, 2) void n1_kernel(
    const float* __restrict__ x,
    const float* __restrict__ W1_in,  const float* __restrict__ b1_in,
    const float* __restrict__ W1_out, const float* __restrict__ b1_out)
{
    const int dir = blockIdx.y;
    const float* W1 = dir ? W1_out : W1_in;
    const float* b1 = dir ? b1_out : b1_in;
    const float* agg = g_agg[dir];
    float* tptr = g_t[dir];

    __shared__ float sA[128][36];
    __shared__ float sW[32][128];
    float acc[8][8];
#pragma unroll
    for (int i = 0; i < 8; i++)
#pragma unroll
        for (int j = 0; j < 8; j++) acc[i][j] = 0.f;

    const int tid = threadIdx.x;
    const int m0  = blockIdx.x * 128;

    gemm_chunk128(x, agg, 16, W1,  0, m0, 1.f, sA, sW, acc, tid);
    gemm_chunk128(x, agg, 16, W1, 32, m0, 1.f, sA, sW, acc, tid);

    const int rg = (tid >> 4) * 8;
    const int cg = (tid & 15) * 8;
#pragma unroll
    for (int i = 0; i < 8; i++) {
        int gr = m0 + rg + i;
        if (gr < N_NODES) {
            float o[8];
#pragma unroll
            for (int j = 0; j < 8; j++)
                o[j] = gelu_exact(acc[i][j] + b1[cg + j]);
            *(float4*)&tptr[(size_t)gr * EMB + cg]     = *(float4*)&o[0];
            *(float4*)&tptr[(size_t)gr * EMB + cg + 4] = *(float4*)&o[4];
        }
    }
}

// ---------------------------------------------------------------------------
// N2: out = 0.5*(t_out@W2_out + b2_out) + 0.5*(t_in@W2_in + b2_in) + x@Wr + br
// ---------------------------------------------------------------------------
__global__ __launch_bounds__(256, 2) void n2_kernel(
    const float* __restrict__ x,
    const float* __restrict__ W2_in,  const float* __restrict__ b2_in,
    const float* __restrict__ W2_out, const float* __restrict__ b2_out,
    const float* __restrict__ Wr,     const float* __restrict__ br,
    float* __restrict__ out)
{
    __shared__ float sA[128][36];
    __shared__ float sW[32][128];
    float acc[8][8];
#pragma unroll
    for (int i = 0; i < 8; i++)
#pragma unroll
        for (int j = 0; j < 8; j++) acc[i][j] = 0.f;

    const int tid = threadIdx.x;
    const int m0  = blockIdx.x * 128;

#pragma unroll 1
    for (int k0 = 0; k0 < 128; k0 += 32)
        gemm_chunk128(g_t[1], nullptr, 32, W2_out, k0, m0, 0.5f, sA, sW, acc, tid);
#pragma unroll 1
    for (int k0 = 0; k0 < 128; k0 += 32)
        gemm_chunk128(g_t[0], nullptr, 32, W2_in, k0, m0, 0.5f, sA, sW, acc, tid);
#pragma unroll 1
    for (int k0 = 0; k0 < 64; k0 += 32)
        gemm_chunk128(x, nullptr, 16, Wr, k0, m0, 1.f, sA, sW, acc, tid);

    const int rg = (tid >> 4) * 8;
    const int cg = (tid & 15) * 8;
#pragma unroll
    for (int i = 0; i < 8; i++) {
        int gr = m0 + rg + i;
        if (gr < N_NODES) {
            float o[8];
#pragma unroll
            for (int j = 0; j < 8; j++) {
                float bias = 0.5f * (b2_out[cg + j] + b2_in[cg + j]) + br[cg + j];
                o[j] = acc[i][j] + bias;
            }
            *(float4*)&out[(size_t)gr * EMB + cg]     = *(float4*)&o[0];
            *(float4*)&out[(size_t)gr * EMB + cg + 4] = *(float4*)&o[4];
        }
    }
}

// ---------------------------------------------------------------------------
// launch
// ---------------------------------------------------------------------------
extern "C" void kernel_launch(void* const* d_in, const int* in_sizes, int n_in,
                              void* d_out, int out_size)
{
    const float* x      = (const float*)d_in[0];
    const int*   ei     = (const int*)d_in[1];
    const float* ea     = (const float*)d_in[2];
    const float* We_in  = (const float*)d_in[3];
    const float* be_in  = (const float*)d_in[4];
    const float* W1_in  = (const float*)d_in[5];
    const float* b1_in  = (const float*)d_in[6];
    const float* W2_in  = (const float*)d_in[7];
    const float* b2_in  = (const float*)d_in[8];
    const float* We_out = (const float*)d_in[9];
    const float* be_out = (const float*)d_in[10];
    const float* W1_out = (const float*)d_in[11];
    const float* b1_out = (const float*)d_in[12];
    const float* W2_out = (const float*)d_in[13];
    const float* b2_out = (const float*)d_in[14];
    const float* Wr     = (const float*)d_in[15];
    const float* br     = (const float*)d_in[16];
    float* out = (float*)d_out;

    // ---- CSR build (per call; graph-capturable, int atomics only) ----
    zero_deg_kernel<<<(N_NODES + 255) / 256, 256>>>();
    count_kernel<<<(N_EDGES + 255) / 256, 256>>>(ei);
    scan1_kernel<<<dim3(NBLK, 2), SCAN_BLK>>>();
    scan2_kernel<<<dim3(1, 2), 256>>>();
    scan3_kernel<<<dim3(NBLK, 2), SCAN_BLK>>>();
    fill_kernel<<<(N_EDGES + 255) / 256, 256>>>(ei);

    // ---- aggregation (atomic-free) ----
    agg_kernel<<<dim3(296, 2), 256>>>(
        (const float2*)x, ei, ea,
        (const float2*)We_in,  (const float2*)be_in,
        (const float2*)We_out, (const float2*)be_out);

    // ---- node MLPs ----
    dim3 ngrid((N_NODES + 127) / 128, 2);
    n1_kernel<<<ngrid, 256>>>(x, W1_in, b1_in, W1_out, b1_out);

    n2_kernel<<<(N_NODES + 127) / 128, 256>>>(
        x, W2_in, b2_in, W2_out, b2_out, Wr, br, out);
}

// round 8
// speedup vs baseline: 1.0696x; 1.0696x over previous
#include <cuda_runtime.h>
#include <math.h>

#define N_NODES 100000
#define N_EDGES 1600000
#define IN_DIM  64
#define EMB     128
#define ED      32

#define SCAN_BLK 512
#define NBLK ((N_NODES + SCAN_BLK - 1) / SCAN_BLK)   // 196

__device__ float g_agg[2][(size_t)N_NODES * IN_DIM];
__device__ float g_t[2][(size_t)N_NODES * EMB];

// CSR scratch
__device__ int  g_deg[2][N_NODES];
__device__ int  g_cur[2][N_NODES];
__device__ int  g_off[2][N_NODES + 1];
__device__ int  g_partial[2][NBLK];
__device__ int  g_pscan[2][NBLK];
__device__ int2 g_elist2[2][N_EDGES];   // {edge id, gather node}

// ---------------------------------------------------------------------------
// CSR build
// ---------------------------------------------------------------------------
__global__ void zero_deg_kernel() {
    int i = blockIdx.x * blockDim.x + threadIdx.x;
    if (i < N_NODES) { g_deg[0][i] = 0; g_deg[1][i] = 0; }
}

__global__ void count_kernel(const int* __restrict__ ei) {
    int e = blockIdx.x * blockDim.x + threadIdx.x;
    if (e < N_EDGES) {
        int s = ei[e];
        int d = ei[N_EDGES + e];
        atomicAdd(&g_deg[0][d], 1);   // conv_in aggregates at dst
        atomicAdd(&g_deg[1][s], 1);   // conv_out aggregates at src
    }
}

__global__ void scan1_kernel() {   // grid (NBLK, 2): block sums
    const int dir = blockIdx.y;
    __shared__ int sred[SCAN_BLK];
    int i = blockIdx.x * SCAN_BLK + threadIdx.x;
    sred[threadIdx.x] = (i < N_NODES) ? g_deg[dir][i] : 0;
    __syncthreads();
    for (int ofs = SCAN_BLK / 2; ofs > 0; ofs >>= 1) {
        if (threadIdx.x < ofs) sred[threadIdx.x] += sred[threadIdx.x + ofs];
        __syncthreads();
    }
    if (threadIdx.x == 0) g_partial[dir][blockIdx.x] = sred[0];
}

__global__ void scan2_kernel() {   // grid (1, 2): scan partials
    const int dir = blockIdx.y;
    __shared__ int sb[2][256];
    int t = threadIdx.x;
    int v = (t < NBLK) ? g_partial[dir][t] : 0;
    sb[0][t] = v;
    __syncthreads();
    int cur = 0;
#pragma unroll
    for (int ofs = 1; ofs < 256; ofs <<= 1) {
        int val = sb[cur][t];
        if (t >= ofs) val += sb[cur][t - ofs];
        sb[cur ^ 1][t] = val;
        __syncthreads();
        cur ^= 1;
    }
    if (t < NBLK) g_pscan[dir][t] = sb[cur][t] - v;   // exclusive
}

__global__ void scan3_kernel() {   // grid (NBLK, 2): final offsets
    const int dir = blockIdx.y;
    __shared__ int sb[2][SCAN_BLK];
    int t = threadIdx.x;
    int i = blockIdx.x * SCAN_BLK + t;
    int v = (i < N_NODES) ? g_deg[dir][i] : 0;
    sb[0][t] = v;
    __syncthreads();
    int cur = 0;
#pragma unroll
    for (int ofs = 1; ofs < SCAN_BLK; ofs <<= 1) {
        int val = sb[cur][t];
        if (t >= ofs) val += sb[cur][t - ofs];
        sb[cur ^ 1][t] = val;
        __syncthreads();
        cur ^= 1;
    }
    int incl = sb[cur][t];
    int base = g_pscan[dir][blockIdx.x];
    if (i < N_NODES) {
        int excl = base + incl - v;
        g_off[dir][i] = excl;
        g_cur[dir][i] = excl;
        if (i == N_NODES - 1) g_off[dir][N_NODES] = base + incl;
    }
}

__global__ void fill_kernel(const int* __restrict__ ei) {
    int e = blockIdx.x * blockDim.x + threadIdx.x;
    if (e < N_EDGES) {
        int s = ei[e];
        int d = ei[N_EDGES + e];
        int p0 = atomicAdd(&g_cur[0][d], 1);
        g_elist2[0][p0] = make_int2(e, s);   // conv_in gathers src
        int p1 = atomicAdd(&g_cur[1][s], 1);
        g_elist2[1][p1] = make_int2(e, d);   // conv_out gathers dst
    }
}

// ---------------------------------------------------------------------------
// Aggregation: warp per node, 4 edges in flight, register accumulation,
// float4 shared reads in the FMA loop, single plain store per node.
// ---------------------------------------------------------------------------
__global__ __launch_bounds__(256, 2) void agg_kernel(
    const float2* __restrict__ x2,        // x as [N_NODES][32] float2
    const float* __restrict__ ea,         // [N_EDGES][32]
    const float2* __restrict__ We_in2,
    const float2* __restrict__ be_in2,
    const float2* __restrict__ We_out2,
    const float2* __restrict__ be_out2)
{
    const int dir  = blockIdx.y;
    const int lane = threadIdx.x & 31;
    const int w    = threadIdx.x >> 5;

    const float2* We2 = dir ? We_out2 : We_in2;
    const float2  bias = dir ? be_out2[lane] : be_in2[lane];
    const int*  off   = g_off[dir];
    const int2* elist = g_elist2[dir];
    float* __restrict__ agg = g_agg[dir];

    float2 wreg[32];
#pragma unroll
    for (int k = 0; k < 32; k++) wreg[k] = We2[k * 32 + lane];

    __shared__ float sEa[8][4][32];

    const int warpGlobal = blockIdx.x * 8 + w;
    const int nwarps = gridDim.x * 8;

    for (int n = warpGlobal; n < N_NODES; n += nwarps) {
        const int beg = off[n];
        const int end = off[n + 1];
        float2 accN = make_float2(0.f, 0.f);

        for (int j0 = beg; j0 < end; j0 += 4) {
            bool hv[4];
            int2 p[4];
#pragma unroll
            for (int i = 0; i < 4; i++) {
                hv[i] = (j0 + i < end);
                p[i] = elist[hv[i] ? (j0 + i) : j0];
            }
            float2 xg[4];
#pragma unroll
            for (int i = 0; i < 4; i++)
                xg[i] = x2[(size_t)p[i].y * 32 + lane];
            float eav[4];
#pragma unroll
            for (int i = 0; i < 4; i++)
                eav[i] = ea[(size_t)p[i].x * 32 + lane];

#pragma unroll
            for (int i = 0; i < 4; i++)
                sEa[w][i][lane] = eav[i];
            __syncwarp();

            float2 m[4];
#pragma unroll
            for (int i = 0; i < 4; i++) {
                m[i].x = xg[i].x + bias.x;
                m[i].y = xg[i].y + bias.y;
            }
#pragma unroll
            for (int k = 0; k < 32; k += 4) {
                float4 a0 = *(const float4*)&sEa[w][0][k];
                float4 a1 = *(const float4*)&sEa[w][1][k];
                float4 a2 = *(const float4*)&sEa[w][2][k];
                float4 a3 = *(const float4*)&sEa[w][3][k];
#pragma unroll
                for (int q = 0; q < 4; q++) {
                    float b0 = q == 0 ? a0.x : q == 1 ? a0.y : q == 2 ? a0.z : a0.w;
                    float b1 = q == 0 ? a1.x : q == 1 ? a1.y : q == 2 ? a1.z : a1.w;
                    float b2 = q == 0 ? a2.x : q == 1 ? a2.y : q == 2 ? a2.z : a2.w;
                    float b3 = q == 0 ? a3.x : q == 1 ? a3.y : q == 2 ? a3.z : a3.w;
                    float2 wk = wreg[k + q];
                    m[0].x = fmaf(b0, wk.x, m[0].x);
                    m[0].y = fmaf(b0, wk.y, m[0].y);
                    m[1].x = fmaf(b1, wk.x, m[1].x);
                    m[1].y = fmaf(b1, wk.y, m[1].y);
                    m[2].x = fmaf(b2, wk.x, m[2].x);
                    m[2].y = fmaf(b2, wk.y, m[2].y);
                    m[3].x = fmaf(b3, wk.x, m[3].x);
                    m[3].y = fmaf(b3, wk.y, m[3].y);
                }
            }
#pragma unroll
            for (int i = 0; i < 4; i++) {
                float mx = fmaxf(m[i].x, 0.f);
                float my = fmaxf(m[i].y, 0.f);
                if (hv[i]) { accN.x += mx; accN.y += my; }
            }
            __syncwarp();
        }
        *(float2*)&agg[(size_t)n * 64 + 2 * lane] = accN;
    }
}

// ---------------------------------------------------------------------------
// GEMM: 128(M) x 128(N) block tile, 256 threads, 8x8 microtile.
// ---------------------------------------------------------------------------
__device__ __forceinline__ void gemm_chunk128(
    const float* __restrict__ A, const float* __restrict__ Aadd, int lda4,
    const float* __restrict__ W, int k0, int m0, float scale,
    float (*sA)[36], float (*sW)[128], float acc[8][8], int tid)
{
    const float4* A4  = (const float4*)A;
    const float4* Aa4 = (const float4*)Aadd;
#pragma unroll
    for (int it = 0; it < 4; ++it) {
        int idx = it * 256 + tid;
        int r   = idx >> 3;
        int cq  = idx & 7;
        float4 v = make_float4(0.f, 0.f, 0.f, 0.f);
        int gr = m0 + r;
        if (gr < N_NODES) {
            v = A4[(size_t)gr * lda4 + (k0 >> 2) + cq];
            if (Aadd) {
                float4 u = Aa4[(size_t)gr * lda4 + (k0 >> 2) + cq];
                v.x += u.x; v.y += u.y; v.z += u.z; v.w += u.w;
            }
            v.x *= scale; v.y *= scale; v.z *= scale; v.w *= scale;
        }
        *(float4*)&sA[r][cq * 4] = v;
    }
    const float4* W4 = (const float4*)W;
#pragma unroll
    for (int it = 0; it < 4; ++it) {
        int idx = it * 256 + tid;
        int kr  = idx >> 5;
        int cq  = idx & 31;
        *(float4*)&sW[kr][cq * 4] = W4[(size_t)(k0 + kr) * 32 + cq];
    }
    __syncthreads();

    const int rg = (tid >> 4) * 8;
    const int cg = (tid & 15) * 8;
#pragma unroll
    for (int k = 0; k < 32; k++) {
        float av[8];
#pragma unroll
        for (int i = 0; i < 8; i++) av[i] = sA[rg + i][k];
        float bv[8];
        *(float4*)&bv[0] = *(const float4*)&sW[k][cg];
        *(float4*)&bv[4] = *(const float4*)&sW[k][cg + 4];
#pragma unroll
        for (int i = 0; i < 8; i++)
#pragma unroll
            for (int j = 0; j < 8; j++)
                acc[i][j] = fmaf(av[i], bv[j], acc[i][j]);
    }
    __syncthreads();
}

__device__ __forceinline__ float gelu_exact(float v) {
    return 0.5f * v * (1.f + erff(v * 0.70710678118654752f));
}

// ---------------------------------------------------------------------------
// N1: t[dir] = gelu((x + agg[dir]) @ W1 + b1)
// ---------------------------------------------------------------------------
__global__ __launch_bounds__(256, 2) void n1_kernel(
    const float* __restrict__ x,
    const float* __restrict__ W1_in,  const float* __restrict__ b1_in,
    const float* __restrict__ W1_out, const float* __restrict__ b1_out)
{
    const int dir = blockIdx.y;
    const float* W1 = dir ? W1_out : W1_in;
    const float* b1 = dir ? b1_out : b1_in;
    const float* agg = g_agg[dir];
    float* tptr = g_t[dir];

    __shared__ float sA[128][36];
    __shared__ float sW[32][128];
    float acc[8][8];
#pragma unroll
    for (int i = 0; i < 8; i++)
#pragma unroll
        for (int j = 0; j < 8; j++) acc[i][j] = 0.f;

    const int tid = threadIdx.x;
    const int m0  = blockIdx.x * 128;

    gemm_chunk128(x, agg, 16, W1,  0, m0, 1.f, sA, sW, acc, tid);
    gemm_chunk128(x, agg, 16, W1, 32, m0, 1.f, sA, sW, acc, tid);

    const int rg = (tid >> 4) * 8;
    const int cg = (tid & 15) * 8;
#pragma unroll
    for (int i = 0; i < 8; i++) {
        int gr = m0 + rg + i;
        if (gr < N_NODES) {
            float o[8];
#pragma unroll
            for (int j = 0; j < 8; j++)
                o[j] = gelu_exact(acc[i][j] + b1[cg + j]);
            *(float4*)&tptr[(size_t)gr * EMB + cg]     = *(float4*)&o[0];
            *(float4*)&tptr[(size_t)gr * EMB + cg + 4] = *(float4*)&o[4];
        }
    }
}

// ---------------------------------------------------------------------------
// N2: out = 0.5*(t_out@W2_out + b2_out) + 0.5*(t_in@W2_in + b2_in) + x@Wr + br
// ---------------------------------------------------------------------------
__global__ __launch_bounds__(256, 2) void n2_kernel(
    const float* __restrict__ x,
    const float* __restrict__ W2_in,  const float* __restrict__ b2_in,
    const float* __restrict__ W2_out, const float* __restrict__ b2_out,
    const float* __restrict__ Wr,     const float* __restrict__ br,
    float* __restrict__ out)
{
    __shared__ float sA[128][36];
    __shared__ float sW[32][128];
    float acc[8][8];
#pragma unroll
    for (int i = 0; i < 8; i++)
#pragma unroll
        for (int j = 0; j < 8; j++) acc[i][j] = 0.f;

    const int tid = threadIdx.x;
    const int m0  = blockIdx.x * 128;

#pragma unroll 1
    for (int k0 = 0; k0 < 128; k0 += 32)
        gemm_chunk128(g_t[1], nullptr, 32, W2_out, k0, m0, 0.5f, sA, sW, acc, tid);
#pragma unroll 1
    for (int k0 = 0; k0 < 128; k0 += 32)
        gemm_chunk128(g_t[0], nullptr, 32, W2_in, k0, m0, 0.5f, sA, sW, acc, tid);
#pragma unroll 1
    for (int k0 = 0; k0 < 64; k0 += 32)
        gemm_chunk128(x, nullptr, 16, Wr, k0, m0, 1.f, sA, sW, acc, tid);

    const int rg = (tid >> 4) * 8;
    const int cg = (tid & 15) * 8;
#pragma unroll
    for (int i = 0; i < 8; i++) {
        int gr = m0 + rg + i;
        if (gr < N_NODES) {
            float o[8];
#pragma unroll
            for (int j = 0; j < 8; j++) {
                float bias = 0.5f * (b2_out[cg + j] + b2_in[cg + j]) + br[cg + j];
                o[j] = acc[i][j] + bias;
            }
            *(float4*)&out[(size_t)gr * EMB + cg]     = *(float4*)&o[0];
            *(float4*)&out[(size_t)gr * EMB + cg + 4] = *(float4*)&o[4];
        }
    }
}

// ---------------------------------------------------------------------------
// launch
// ---------------------------------------------------------------------------
extern "C" void kernel_launch(void* const* d_in, const int* in_sizes, int n_in,
                              void* d_out, int out_size)
{
    const float* x      = (const float*)d_in[0];
    const int*   ei     = (const int*)d_in[1];
    const float* ea     = (const float*)d_in[2];
    const float* We_in  = (const float*)d_in[3];
    const float* be_in  = (const float*)d_in[4];
    const float* W1_in  = (const float*)d_in[5];
    const float* b1_in  = (const float*)d_in[6];
    const float* W2_in  = (const float*)d_in[7];
    const float* b2_in  = (const float*)d_in[8];
    const float* We_out = (const float*)d_in[9];
    const float* be_out = (const float*)d_in[10];
    const float* W1_out = (const float*)d_in[11];
    const float* b1_out = (const float*)d_in[12];
    const float* W2_out = (const float*)d_in[13];
    const float* b2_out = (const float*)d_in[14];
    const float* Wr     = (const float*)d_in[15];
    const float* br     = (const float*)d_in[16];
    float* out = (float*)d_out;

    // ---- CSR build ----
    zero_deg_kernel<<<(N_NODES + 255) / 256, 256>>>();
    count_kernel<<<(N_EDGES + 255) / 256, 256>>>(ei);
    scan1_kernel<<<dim3(NBLK, 2), SCAN_BLK>>>();
    scan2_kernel<<<dim3(1, 2), 256>>>();
    scan3_kernel<<<dim3(NBLK, 2), SCAN_BLK>>>();
    fill_kernel<<<(N_EDGES + 255) / 256, 256>>>(ei);

    // ---- aggregation (atomic-free) ----
    agg_kernel<<<dim3(296, 2), 256>>>(
        (const float2*)x, ea,
        (const float2*)We_in,  (const float2*)be_in,
        (const float2*)We_out, (const float2*)be_out);

    // ---- node MLPs ----
    dim3 ngrid((N_NODES + 127) / 128, 2);
    n1_kernel<<<ngrid, 256>>>(x, W1_in, b1_in, W1_out, b1_out);

    n2_kernel<<<(N_NODES + 127) / 128, 256>>>(
        x, W2_in, b2_in, W2_out, b2_out, Wr, br, out);
}

// round 9
// speedup vs baseline: 1.1160x; 1.0433x over previous
#include <cuda_runtime.h>
#include <math.h>

#define N_NODES 100000
#define N_EDGES 1600000
#define IN_DIM  64
#define EMB     128
#define ED      32

#define SCAN_BLK 512
#define NBLK ((N_NODES + SCAN_BLK - 1) / SCAN_BLK)   // 196

typedef unsigned long long u64;

__device__ __forceinline__ u64 pack2(float x, float y) {
    u64 r; asm("mov.b64 %0, {%1, %2};" : "=l"(r) : "f"(x), "f"(y)); return r;
}
__device__ __forceinline__ void unpack2(u64 v, float& x, float& y) {
    asm("mov.b64 {%0, %1}, %2;" : "=f"(x), "=f"(y) : "l"(v));
}
__device__ __forceinline__ u64 ffma2(u64 a, u64 b, u64 c) {   // a*b+c (2x fp32)
    u64 d; asm("fma.rn.f32x2 %0, %1, %2, %3;" : "=l"(d) : "l"(a), "l"(b), "l"(c));
    return d;
}
__device__ __forceinline__ u64 fadd2(u64 a, u64 b) {
    u64 d; asm("add.rn.f32x2 %0, %1, %2;" : "=l"(d) : "l"(a), "l"(b));
    return d;
}

__device__ float g_agg[2][(size_t)N_NODES * IN_DIM];
__device__ float g_t[2][(size_t)N_NODES * EMB];

// CSR scratch
__device__ int  g_deg[2][N_NODES];
__device__ int  g_cur[2][N_NODES];
__device__ int  g_off[2][N_NODES + 1];
__device__ int  g_partial[2][NBLK];
__device__ int  g_pscan[2][NBLK];
__device__ int2 g_elist2[2][N_EDGES];   // {edge id, gather node}

// ---------------------------------------------------------------------------
// CSR build
// ---------------------------------------------------------------------------
__global__ void zero_deg_kernel() {
    int i = blockIdx.x * blockDim.x + threadIdx.x;
    if (i < N_NODES) { g_deg[0][i] = 0; g_deg[1][i] = 0; }
}

__global__ void count_kernel(const int* __restrict__ ei) {
    int e = blockIdx.x * blockDim.x + threadIdx.x;
    if (e < N_EDGES) {
        int s = ei[e];
        int d = ei[N_EDGES + e];
        atomicAdd(&g_deg[0][d], 1);
        atomicAdd(&g_deg[1][s], 1);
    }
}

__global__ void scan1_kernel() {
    const int dir = blockIdx.y;
    __shared__ int sred[SCAN_BLK];
    int i = blockIdx.x * SCAN_BLK + threadIdx.x;
    sred[threadIdx.x] = (i < N_NODES) ? g_deg[dir][i] : 0;
    __syncthreads();
    for (int ofs = SCAN_BLK / 2; ofs > 0; ofs >>= 1) {
        if (threadIdx.x < ofs) sred[threadIdx.x] += sred[threadIdx.x + ofs];
        __syncthreads();
    }
    if (threadIdx.x == 0) g_partial[dir][blockIdx.x] = sred[0];
}

__global__ void scan2_kernel() {
    const int dir = blockIdx.y;
    __shared__ int sb[2][256];
    int t = threadIdx.x;
    int v = (t < NBLK) ? g_partial[dir][t] : 0;
    sb[0][t] = v;
    __syncthreads();
    int cur = 0;
#pragma unroll
    for (int ofs = 1; ofs < 256; ofs <<= 1) {
        int val = sb[cur][t];
        if (t >= ofs) val += sb[cur][t - ofs];
        sb[cur ^ 1][t] = val;
        __syncthreads();
        cur ^= 1;
    }
    if (t < NBLK) g_pscan[dir][t] = sb[cur][t] - v;
}

__global__ void scan3_kernel() {
    const int dir = blockIdx.y;
    __shared__ int sb[2][SCAN_BLK];
    int t = threadIdx.x;
    int i = blockIdx.x * SCAN_BLK + t;
    int v = (i < N_NODES) ? g_deg[dir][i] : 0;
    sb[0][t] = v;
    __syncthreads();
    int cur = 0;
#pragma unroll
    for (int ofs = 1; ofs < SCAN_BLK; ofs <<= 1) {
        int val = sb[cur][t];
        if (t >= ofs) val += sb[cur][t - ofs];
        sb[cur ^ 1][t] = val;
        __syncthreads();
        cur ^= 1;
    }
    int incl = sb[cur][t];
    int base = g_pscan[dir][blockIdx.x];
    if (i < N_NODES) {
        int excl = base + incl - v;
        g_off[dir][i] = excl;
        g_cur[dir][i] = excl;
        if (i == N_NODES - 1) g_off[dir][N_NODES] = base + incl;
    }
}

__global__ void fill_kernel(const int* __restrict__ ei) {
    int e = blockIdx.x * blockDim.x + threadIdx.x;
    if (e < N_EDGES) {
        int s = ei[e];
        int d = ei[N_EDGES + e];
        int p0 = atomicAdd(&g_cur[0][d], 1);
        g_elist2[0][p0] = make_int2(e, s);
        int p1 = atomicAdd(&g_cur[1][s], 1);
        g_elist2[1][p1] = make_int2(e, d);
    }
}

// ---------------------------------------------------------------------------
// Aggregation: warp per node, 4 edges in flight, packed f32x2 FMA.
// ea staged DUPLICATED ({a,a}) so one LDS.128 feeds 2 k-steps directly.
// ---------------------------------------------------------------------------
__global__ __launch_bounds__(256, 2) void agg_kernel(
    const float2* __restrict__ x2,        // x as [N_NODES][32] float2
    const float* __restrict__ ea,         // [N_EDGES][32]
    const float2* __restrict__ We_in2,
    const float2* __restrict__ be_in2,
    const float2* __restrict__ We_out2,
    const float2* __restrict__ be_out2)
{
    const int dir  = blockIdx.y;
    const int lane = threadIdx.x & 31;
    const int w    = threadIdx.x >> 5;

    const float2* We2 = dir ? We_out2 : We_in2;
    const float2  biasv = dir ? be_out2[lane] : be_in2[lane];
    const u64 biasP = pack2(biasv.x, biasv.y);
    const int*  off   = g_off[dir];
    const int2* elist = g_elist2[dir];
    float* __restrict__ agg = g_agg[dir];

    u64 wreg2[32];
#pragma unroll
    for (int k = 0; k < 32; k++) {
        float2 wv = We2[k * 32 + lane];
        wreg2[k] = pack2(wv.x, wv.y);
    }

    __shared__ float2 sEaD[8][4][32];   // duplicated pairs {a,a}

    const int warpGlobal = blockIdx.x * 8 + w;
    const int nwarps = gridDim.x * 8;

    for (int n = warpGlobal; n < N_NODES; n += nwarps) {
        const int beg = off[n];
        const int end = off[n + 1];
        float2 accN = make_float2(0.f, 0.f);

        for (int j0 = beg; j0 < end; j0 += 4) {
            bool hv[4];
            int2 p[4];
#pragma unroll
            for (int i = 0; i < 4; i++) {
                hv[i] = (j0 + i < end);
                p[i] = elist[hv[i] ? (j0 + i) : j0];
            }
            float2 xg[4];
#pragma unroll
            for (int i = 0; i < 4; i++)
                xg[i] = x2[(size_t)p[i].y * 32 + lane];
            float eav[4];
#pragma unroll
            for (int i = 0; i < 4; i++)
                eav[i] = ea[(size_t)p[i].x * 32 + lane];

#pragma unroll
            for (int i = 0; i < 4; i++)
                sEaD[w][i][lane] = make_float2(eav[i], eav[i]);
            __syncwarp();

            u64 m[4];
#pragma unroll
            for (int i = 0; i < 4; i++)
                m[i] = fadd2(pack2(xg[i].x, xg[i].y), biasP);

#pragma unroll
            for (int k0 = 0; k0 < 32; k0 += 2) {
#pragma unroll
                for (int i = 0; i < 4; i++) {
                    ulonglong2 ap = *(const ulonglong2*)&sEaD[w][i][k0];
                    m[i] = ffma2(ap.x, wreg2[k0],     m[i]);
                    m[i] = ffma2(ap.y, wreg2[k0 + 1], m[i]);
                }
            }

#pragma unroll
            for (int i = 0; i < 4; i++) {
                float mx, my;
                unpack2(m[i], mx, my);
                mx = fmaxf(mx, 0.f);
                my = fmaxf(my, 0.f);
                if (hv[i]) { accN.x += mx; accN.y += my; }
            }
            __syncwarp();
        }
        *(float2*)&agg[(size_t)n * 64 + 2 * lane] = accN;
    }
}

// ---------------------------------------------------------------------------
// GEMM: 128x128 block tile, 256 threads, 8x8 microtile via packed f32x2.
// acc2[i][jp] holds output cols {cg+2jp, cg+2jp+1}.
// ---------------------------------------------------------------------------
__device__ __forceinline__ void gemm_chunk128(
    const float* __restrict__ A, const float* __restrict__ Aadd, int lda4,
    const float* __restrict__ W, int k0, int m0, float scale,
    float (*sA)[36], float (*sW)[128], u64 acc2[8][4], int tid)
{
    const float4* A4  = (const float4*)A;
    const float4* Aa4 = (const float4*)Aadd;
#pragma unroll
    for (int it = 0; it < 4; ++it) {
        int idx = it * 256 + tid;
        int r   = idx >> 3;
        int cq  = idx & 7;
        float4 v = make_float4(0.f, 0.f, 0.f, 0.f);
        int gr = m0 + r;
        if (gr < N_NODES) {
            v = A4[(size_t)gr * lda4 + (k0 >> 2) + cq];
            if (Aadd) {
                float4 u = Aa4[(size_t)gr * lda4 + (k0 >> 2) + cq];
                v.x += u.x; v.y += u.y; v.z += u.z; v.w += u.w;
            }
            v.x *= scale; v.y *= scale; v.z *= scale; v.w *= scale;
        }
        *(float4*)&sA[r][cq * 4] = v;
    }
    const float4* W4 = (const float4*)W;
#pragma unroll
    for (int it = 0; it < 4; ++it) {
        int idx = it * 256 + tid;
        int kr  = idx >> 5;
        int cq  = idx & 31;
        *(float4*)&sW[kr][cq * 4] = W4[(size_t)(k0 + kr) * 32 + cq];
    }
    __syncthreads();

    const int rg = (tid >> 4) * 8;
    const int cg = (tid & 15) * 8;
#pragma unroll
    for (int kk = 0; kk < 32; kk += 2) {
        // bv pairs for two k-steps: consecutive floats form packed pairs
        ulonglong2 b0a = *(const ulonglong2*)&sW[kk][cg];
        ulonglong2 b0b = *(const ulonglong2*)&sW[kk][cg + 4];
        ulonglong2 b1a = *(const ulonglong2*)&sW[kk + 1][cg];
        ulonglong2 b1b = *(const ulonglong2*)&sW[kk + 1][cg + 4];
        u64 bv0[4] = { b0a.x, b0a.y, b0b.x, b0b.y };
        u64 bv1[4] = { b1a.x, b1a.y, b1b.x, b1b.y };
#pragma unroll
        for (int i = 0; i < 8; i++) {
            float2 a2 = *(const float2*)&sA[rg + i][kk];
            u64 aP0 = pack2(a2.x, a2.x);
            u64 aP1 = pack2(a2.y, a2.y);
#pragma unroll
            for (int jp = 0; jp < 4; jp++) {
                acc2[i][jp] = ffma2(aP0, bv0[jp], acc2[i][jp]);
                acc2[i][jp] = ffma2(aP1, bv1[jp], acc2[i][jp]);
            }
        }
    }
    __syncthreads();
}

__device__ __forceinline__ float gelu_exact(float v) {
    return 0.5f * v * (1.f + erff(v * 0.70710678118654752f));
}

// ---------------------------------------------------------------------------
// N1: t[dir] = gelu((x + agg[dir]) @ W1 + b1)
// ---------------------------------------------------------------------------
__global__ __launch_bounds__(256, 2) void n1_kernel(
    const float* __restrict__ x,
    const float* __restrict__ W1_in,  const float* __restrict__ b1_in,
    const float* __restrict__ W1_out, const float* __restrict__ b1_out)
{
    const int dir = blockIdx.y;
    const float* W1 = dir ? W1_out : W1_in;
    const float* b1 = dir ? b1_out : b1_in;
    const float* agg = g_agg[dir];
    float* tptr = g_t[dir];

    __shared__ float sA[128][36];
    __shared__ float sW[32][128];
    u64 acc2[8][4];
#pragma unroll
    for (int i = 0; i < 8; i++)
#pragma unroll
        for (int j = 0; j < 4; j++) acc2[i][j] = 0ull;

    const int tid = threadIdx.x;
    const int m0  = blockIdx.x * 128;

    gemm_chunk128(x, agg, 16, W1,  0, m0, 1.f, sA, sW, acc2, tid);
    gemm_chunk128(x, agg, 16, W1, 32, m0, 1.f, sA, sW, acc2, tid);

    const int rg = (tid >> 4) * 8;
    const int cg = (tid & 15) * 8;
#pragma unroll
    for (int i = 0; i < 8; i++) {
        int gr = m0 + rg + i;
        if (gr < N_NODES) {
            float o[8];
#pragma unroll
            for (int jp = 0; jp < 4; jp++) {
                float lo, hi;
                unpack2(acc2[i][jp], lo, hi);
                o[2 * jp]     = gelu_exact(lo + b1[cg + 2 * jp]);
                o[2 * jp + 1] = gelu_exact(hi + b1[cg + 2 * jp + 1]);
            }
            *(float4*)&tptr[(size_t)gr * EMB + cg]     = *(float4*)&o[0];
            *(float4*)&tptr[(size_t)gr * EMB + cg + 4] = *(float4*)&o[4];
        }
    }
}

// ---------------------------------------------------------------------------
// N2: out = 0.5*(t_out@W2_out + b2_out) + 0.5*(t_in@W2_in + b2_in) + x@Wr + br
// ---------------------------------------------------------------------------
__global__ __launch_bounds__(256, 2) void n2_kernel(
    const float* __restrict__ x,
    const float* __restrict__ W2_in,  const float* __restrict__ b2_in,
    const float* __restrict__ W2_out, const float* __restrict__ b2_out,
    const float* __restrict__ Wr,     const float* __restrict__ br,
    float* __restrict__ out)
{
    __shared__ float sA[128][36];
    __shared__ float sW[32][128];
    u64 acc2[8][4];
#pragma unroll
    for (int i = 0; i < 8; i++)
#pragma unroll
        for (int j = 0; j < 4; j++) acc2[i][j] = 0ull;

    const int tid = threadIdx.x;
    const int m0  = blockIdx.x * 128;

#pragma unroll 1
    for (int k0 = 0; k0 < 128; k0 += 32)
        gemm_chunk128(g_t[1], nullptr, 32, W2_out, k0, m0, 0.5f, sA, sW, acc2, tid);
#pragma unroll 1
    for (int k0 = 0; k0 < 128; k0 += 32)
        gemm_chunk128(g_t[0], nullptr, 32, W2_in, k0, m0, 0.5f, sA, sW, acc2, tid);
#pragma unroll 1
    for (int k0 = 0; k0 < 64; k0 += 32)
        gemm_chunk128(x, nullptr, 16, Wr, k0, m0, 1.f, sA, sW, acc2, tid);

    const int rg = (tid >> 4) * 8;
    const int cg = (tid & 15) * 8;
#pragma unroll
    for (int i = 0; i < 8; i++) {
        int gr = m0 + rg + i;
        if (gr < N_NODES) {
            float o[8];
#pragma unroll
            for (int jp = 0; jp < 4; jp++) {
                float lo, hi;
                unpack2(acc2[i][jp], lo, hi);
                int c0 = cg + 2 * jp;
                o[2 * jp]     = lo + 0.5f * (b2_out[c0] + b2_in[c0]) + br[c0];
                o[2 * jp + 1] = hi + 0.5f * (b2_out[c0 + 1] + b2_in[c0 + 1]) + br[c0 + 1];
            }
            *(float4*)&out[(size_t)gr * EMB + cg]     = *(float4*)&o[0];
            *(float4*)&out[(size_t)gr * EMB + cg + 4] = *(float4*)&o[4];
        }
    }
}

// ---------------------------------------------------------------------------
// launch
// ---------------------------------------------------------------------------
extern "C" void kernel_launch(void* const* d_in, const int* in_sizes, int n_in,
                              void* d_out, int out_size)
{
    const float* x      = (const float*)d_in[0];
    const int*   ei     = (const int*)d_in[1];
    const float* ea     = (const float*)d_in[2];
    const float* We_in  = (const float*)d_in[3];
    const float* be_in  = (const float*)d_in[4];
    const float* W1_in  = (const float*)d_in[5];
    const float* b1_in  = (const float*)d_in[6];
    const float* W2_in  = (const float*)d_in[7];
    const float* b2_in  = (const float*)d_in[8];
    const float* We_out = (const float*)d_in[9];
    const float* be_out = (const float*)d_in[10];
    const float* W1_out = (const float*)d_in[11];
    const float* b1_out = (const float*)d_in[12];
    const float* W2_out = (const float*)d_in[13];
    const float* b2_out = (const float*)d_in[14];
    const float* Wr     = (const float*)d_in[15];
    const float* br     = (const float*)d_in[16];
    float* out = (float*)d_out;

    // ---- CSR build ----
    zero_deg_kernel<<<(N_NODES + 255) / 256, 256>>>();
    count_kernel<<<(N_EDGES + 255) / 256, 256>>>(ei);
    scan1_kernel<<<dim3(NBLK, 2), SCAN_BLK>>>();
    scan2_kernel<<<dim3(1, 2), 256>>>();
    scan3_kernel<<<dim3(NBLK, 2), SCAN_BLK>>>();
    fill_kernel<<<(N_EDGES + 255) / 256, 256>>>(ei);

    // ---- aggregation (atomic-free, f32x2) ----
    agg_kernel<<<dim3(296, 2), 256>>>(
        (const float2*)x, ea,
        (const float2*)We_in,  (const float2*)be_in,
        (const float2*)We_out, (const float2*)be_out);

    // ---- node MLPs (f32x2) ----
    dim3 ngrid((N_NODES + 127) / 128, 2);
    n1_kernel<<<ngrid, 256>>>(x, W1_in, b1_in, W1_out, b1_out);

    n2_kernel<<<(N_NODES + 127) / 128, 256>>>(
        x, W2_in, b2_in, W2_out, b2_out, Wr, br, out);
}

// round 10
// speedup vs baseline: 1.1763x; 1.0540x over previous
#include <cuda_runtime.h>
#include <math.h>

#define N_NODES 100000
#define N_EDGES 1600000
#define IN_DIM  64
#define EMB     128
#define ED      32

#define SCAN_BLK 512
#define NBLK ((N_NODES + SCAN_BLK - 1) / SCAN_BLK)   // 196

typedef unsigned long long u64;

__device__ __forceinline__ u64 pack2(float x, float y) {
    u64 r; asm("mov.b64 %0, {%1, %2};" : "=l"(r) : "f"(x), "f"(y)); return r;
}
__device__ __forceinline__ void unpack2(u64 v, float& x, float& y) {
    asm("mov.b64 {%0, %1}, %2;" : "=f"(x), "=f"(y) : "l"(v));
}
__device__ __forceinline__ u64 ffma2(u64 a, u64 b, u64 c) {   // a*b+c (2x fp32)
    u64 d; asm("fma.rn.f32x2 %0, %1, %2, %3;" : "=l"(d) : "l"(a), "l"(b), "l"(c));
    return d;
}
__device__ __forceinline__ u64 fadd2(u64 a, u64 b) {
    u64 d; asm("add.rn.f32x2 %0, %1, %2;" : "=l"(d) : "l"(a), "l"(b));
    return d;
}

__device__ float g_agg[2][(size_t)N_NODES * IN_DIM];
__device__ float g_t[2][(size_t)N_NODES * EMB];

// CSR scratch
__device__ int  g_deg[2][N_NODES];
__device__ int  g_cur[2][N_NODES];
__device__ int  g_off[2][N_NODES + 1];
__device__ int  g_partial[2][NBLK];
__device__ int  g_pscan[2][NBLK];
__device__ int2 g_elist2[2][N_EDGES];   // {edge id, gather node}

// ---------------------------------------------------------------------------
// CSR build
// ---------------------------------------------------------------------------
__global__ void zero_deg_kernel() {
    int i = blockIdx.x * blockDim.x + threadIdx.x;
    if (i < N_NODES) { g_deg[0][i] = 0; g_deg[1][i] = 0; }
}

__global__ void count_kernel(const int* __restrict__ ei) {
    int e = blockIdx.x * blockDim.x + threadIdx.x;
    if (e < N_EDGES) {
        int s = ei[e];
        int d = ei[N_EDGES + e];
        atomicAdd(&g_deg[0][d], 1);
        atomicAdd(&g_deg[1][s], 1);
    }
}

__global__ void scan1_kernel() {
    const int dir = blockIdx.y;
    __shared__ int sred[SCAN_BLK];
    int i = blockIdx.x * SCAN_BLK + threadIdx.x;
    sred[threadIdx.x] = (i < N_NODES) ? g_deg[dir][i] : 0;
    __syncthreads();
    for (int ofs = SCAN_BLK / 2; ofs > 0; ofs >>= 1) {
        if (threadIdx.x < ofs) sred[threadIdx.x] += sred[threadIdx.x + ofs];
        __syncthreads();
    }
    if (threadIdx.x == 0) g_partial[dir][blockIdx.x] = sred[0];
}

__global__ void scan2_kernel() {
    const int dir = blockIdx.y;
    __shared__ int sb[2][256];
    int t = threadIdx.x;
    int v = (t < NBLK) ? g_partial[dir][t] : 0;
    sb[0][t] = v;
    __syncthreads();
    int cur = 0;
#pragma unroll
    for (int ofs = 1; ofs < 256; ofs <<= 1) {
        int val = sb[cur][t];
        if (t >= ofs) val += sb[cur][t - ofs];
        sb[cur ^ 1][t] = val;
        __syncthreads();
        cur ^= 1;
    }
    if (t < NBLK) g_pscan[dir][t] = sb[cur][t] - v;
}

__global__ void scan3_kernel() {
    const int dir = blockIdx.y;
    __shared__ int sb[2][SCAN_BLK];
    int t = threadIdx.x;
    int i = blockIdx.x * SCAN_BLK + t;
    int v = (i < N_NODES) ? g_deg[dir][i] : 0;
    sb[0][t] = v;
    __syncthreads();
    int cur = 0;
#pragma unroll
    for (int ofs = 1; ofs < SCAN_BLK; ofs <<= 1) {
        int val = sb[cur][t];
        if (t >= ofs) val += sb[cur][t - ofs];
        sb[cur ^ 1][t] = val;
        __syncthreads();
        cur ^= 1;
    }
    int incl = sb[cur][t];
    int base = g_pscan[dir][blockIdx.x];
    if (i < N_NODES) {
        int excl = base + incl - v;
        g_off[dir][i] = excl;
        g_cur[dir][i] = excl;
        if (i == N_NODES - 1) g_off[dir][N_NODES] = base + incl;
    }
}

__global__ void fill_kernel(const int* __restrict__ ei) {
    int e = blockIdx.x * blockDim.x + threadIdx.x;
    if (e < N_EDGES) {
        int s = ei[e];
        int d = ei[N_EDGES + e];
        int p0 = atomicAdd(&g_cur[0][d], 1);
        g_elist2[0][p0] = make_int2(e, s);
        int p1 = atomicAdd(&g_cur[1][s], 1);
        g_elist2[1][p1] = make_int2(e, d);
    }
}

// ---------------------------------------------------------------------------
// Aggregation: warp per node, 4 edges per group, SOFTWARE PIPELINED:
// group j+1's global loads issue before group j's compute. f32x2 math.
// ---------------------------------------------------------------------------
#define LOAD_GROUP(j0, P, XG, EV)                                  \
    {                                                              \
        _Pragma("unroll")                                          \
        for (int i = 0; i < 4; i++) {                              \
            int jj = (j0 + i < end) ? (j0 + i) : (j0);             \
            P[i] = elist[jj];                                      \
        }                                                          \
        _Pragma("unroll")                                          \
        for (int i = 0; i < 4; i++)                                \
            XG[i] = x2[(size_t)P[i].y * 32 + lane];                \
        _Pragma("unroll")                                          \
        for (int i = 0; i < 4; i++)                                \
            EV[i] = ea[(size_t)P[i].x * 32 + lane];                \
    }

__global__ __launch_bounds__(256, 2) void agg_kernel(
    const float2* __restrict__ x2,        // x as [N_NODES][32] float2
    const float* __restrict__ ea,         // [N_EDGES][32]
    const float2* __restrict__ We_in2,
    const float2* __restrict__ be_in2,
    const float2* __restrict__ We_out2,
    const float2* __restrict__ be_out2)
{
    const int dir  = blockIdx.y;
    const int lane = threadIdx.x & 31;
    const int w    = threadIdx.x >> 5;

    const float2* We2 = dir ? We_out2 : We_in2;
    const float2  biasv = dir ? be_out2[lane] : be_in2[lane];
    const u64 biasP = pack2(biasv.x, biasv.y);
    const int*  off   = g_off[dir];
    const int2* elist = g_elist2[dir];
    float* __restrict__ agg = g_agg[dir];

    u64 wreg2[32];
#pragma unroll
    for (int k = 0; k < 32; k++) {
        float2 wv = We2[k * 32 + lane];
        wreg2[k] = pack2(wv.x, wv.y);
    }

    __shared__ float2 sEaD[8][4][32];   // duplicated pairs {a,a}

    const int warpGlobal = blockIdx.x * 8 + w;
    const int nwarps = gridDim.x * 8;

    for (int n = warpGlobal; n < N_NODES; n += nwarps) {
        const int beg = off[n];
        const int end = off[n + 1];
        float2 accN = make_float2(0.f, 0.f);

        if (beg < end) {
            int2   pc[4];  float2 xc[4];  float ec[4];
            LOAD_GROUP(beg, pc, xc, ec);

            for (int j0 = beg; j0 < end; j0 += 4) {
                const int jn = j0 + 4;
                int2   pn[4];  float2 xn[4];  float en[4];
                if (jn < end) LOAD_GROUP(jn, pn, xn, en);   // prefetch next

                // stage current ea (duplicated) and compute
#pragma unroll
                for (int i = 0; i < 4; i++)
                    sEaD[w][i][lane] = make_float2(ec[i], ec[i]);
                __syncwarp();

                u64 m[4];
#pragma unroll
                for (int i = 0; i < 4; i++)
                    m[i] = fadd2(pack2(xc[i].x, xc[i].y), biasP);

#pragma unroll
                for (int k0 = 0; k0 < 32; k0 += 2) {
#pragma unroll
                    for (int i = 0; i < 4; i++) {
                        ulonglong2 ap = *(const ulonglong2*)&sEaD[w][i][k0];
                        m[i] = ffma2(ap.x, wreg2[k0],     m[i]);
                        m[i] = ffma2(ap.y, wreg2[k0 + 1], m[i]);
                    }
                }

#pragma unroll
                for (int i = 0; i < 4; i++) {
                    float mx, my;
                    unpack2(m[i], mx, my);
                    mx = fmaxf(mx, 0.f);
                    my = fmaxf(my, 0.f);
                    if (j0 + i < end) { accN.x += mx; accN.y += my; }
                }
                __syncwarp();

                // rotate buffers
#pragma unroll
                for (int i = 0; i < 4; i++) {
                    pc[i] = pn[i]; xc[i] = xn[i]; ec[i] = en[i];
                }
            }
        }
        *(float2*)&agg[(size_t)n * 64 + 2 * lane] = accN;
    }
}

// ---------------------------------------------------------------------------
// GEMM: 128x128 block tile, 256 threads, 8x8 microtile via packed f32x2.
// ---------------------------------------------------------------------------
__device__ __forceinline__ void gemm_chunk128(
    const float* __restrict__ A, const float* __restrict__ Aadd, int lda4,
    const float* __restrict__ W, int k0, int m0, float scale,
    float (*sA)[36], float (*sW)[128], u64 acc2[8][4], int tid)
{
    const float4* A4  = (const float4*)A;
    const float4* Aa4 = (const float4*)Aadd;
#pragma unroll
    for (int it = 0; it < 4; ++it) {
        int idx = it * 256 + tid;
        int r   = idx >> 3;
        int cq  = idx & 7;
        float4 v = make_float4(0.f, 0.f, 0.f, 0.f);
        int gr = m0 + r;
        if (gr < N_NODES) {
            v = A4[(size_t)gr * lda4 + (k0 >> 2) + cq];
            if (Aadd) {
                float4 u = Aa4[(size_t)gr * lda4 + (k0 >> 2) + cq];
                v.x += u.x; v.y += u.y; v.z += u.z; v.w += u.w;
            }
            v.x *= scale; v.y *= scale; v.z *= scale; v.w *= scale;
        }
        *(float4*)&sA[r][cq * 4] = v;
    }
    const float4* W4 = (const float4*)W;
#pragma unroll
    for (int it = 0; it < 4; ++it) {
        int idx = it * 256 + tid;
        int kr  = idx >> 5;
        int cq  = idx & 31;
        *(float4*)&sW[kr][cq * 4] = W4[(size_t)(k0 + kr) * 32 + cq];
    }
    __syncthreads();

    const int rg = (tid >> 4) * 8;
    const int cg = (tid & 15) * 8;
#pragma unroll
    for (int kk = 0; kk < 32; kk += 2) {
        ulonglong2 b0a = *(const ulonglong2*)&sW[kk][cg];
        ulonglong2 b0b = *(const ulonglong2*)&sW[kk][cg + 4];
        ulonglong2 b1a = *(const ulonglong2*)&sW[kk + 1][cg];
        ulonglong2 b1b = *(const ulonglong2*)&sW[kk + 1][cg + 4];
        u64 bv0[4] = { b0a.x, b0a.y, b0b.x, b0b.y };
        u64 bv1[4] = { b1a.x, b1a.y, b1b.x, b1b.y };
#pragma unroll
        for (int i = 0; i < 8; i++) {
            float2 a2 = *(const float2*)&sA[rg + i][kk];
            u64 aP0 = pack2(a2.x, a2.x);
            u64 aP1 = pack2(a2.y, a2.y);
#pragma unroll
            for (int jp = 0; jp < 4; jp++) {
                acc2[i][jp] = ffma2(aP0, bv0[jp], acc2[i][jp]);
                acc2[i][jp] = ffma2(aP1, bv1[jp], acc2[i][jp]);
            }
        }
    }
    __syncthreads();
}

__device__ __forceinline__ float gelu_exact(float v) {
    return 0.5f * v * (1.f + erff(v * 0.70710678118654752f));
}

// ---------------------------------------------------------------------------
// N1: t[dir] = gelu((x + agg[dir]) @ W1 + b1)
// ---------------------------------------------------------------------------
__global__ __launch_bounds__(256, 2) void n1_kernel(
    const float* __restrict__ x,
    const float* __restrict__ W1_in,  const float* __restrict__ b1_in,
    const float* __restrict__ W1_out, const float* __restrict__ b1_out)
{
    const int dir = blockIdx.y;
    const float* W1 = dir ? W1_out : W1_in;
    const float* b1 = dir ? b1_out : b1_in;
    const float* agg = g_agg[dir];
    float* tptr = g_t[dir];

    __shared__ float sA[128][36];
    __shared__ float sW[32][128];
    u64 acc2[8][4];
#pragma unroll
    for (int i = 0; i < 8; i++)
#pragma unroll
        for (int j = 0; j < 4; j++) acc2[i][j] = 0ull;

    const int tid = threadIdx.x;
    const int m0  = blockIdx.x * 128;

    gemm_chunk128(x, agg, 16, W1,  0, m0, 1.f, sA, sW, acc2, tid);
    gemm_chunk128(x, agg, 16, W1, 32, m0, 1.f, sA, sW, acc2, tid);

    const int rg = (tid >> 4) * 8;
    const int cg = (tid & 15) * 8;
#pragma unroll
    for (int i = 0; i < 8; i++) {
        int gr = m0 + rg + i;
        if (gr < N_NODES) {
            float o[8];
#pragma unroll
            for (int jp = 0; jp < 4; jp++) {
                float lo, hi;
                unpack2(acc2[i][jp], lo, hi);
                o[2 * jp]     = gelu_exact(lo + b1[cg + 2 * jp]);
                o[2 * jp + 1] = gelu_exact(hi + b1[cg + 2 * jp + 1]);
            }
            *(float4*)&tptr[(size_t)gr * EMB + cg]     = *(float4*)&o[0];
            *(float4*)&tptr[(size_t)gr * EMB + cg + 4] = *(float4*)&o[4];
        }
    }
}

// ---------------------------------------------------------------------------
// N2: out = 0.5*(t_out@W2_out + b2_out) + 0.5*(t_in@W2_in + b2_in) + x@Wr + br
// ---------------------------------------------------------------------------
__global__ __launch_bounds__(256, 2) void n2_kernel(
    const float* __restrict__ x,
    const float* __restrict__ W2_in,  const float* __restrict__ b2_in,
    const float* __restrict__ W2_out, const float* __restrict__ b2_out,
    const float* __restrict__ Wr,     const float* __restrict__ br,
    float* __restrict__ out)
{
    __shared__ float sA[128][36];
    __shared__ float sW[32][128];
    u64 acc2[8][4];
#pragma unroll
    for (int i = 0; i < 8; i++)
#pragma unroll
        for (int j = 0; j < 4; j++) acc2[i][j] = 0ull;

    const int tid = threadIdx.x;
    const int m0  = blockIdx.x * 128;

#pragma unroll 1
    for (int k0 = 0; k0 < 128; k0 += 32)
        gemm_chunk128(g_t[1], nullptr, 32, W2_out, k0, m0, 0.5f, sA, sW, acc2, tid);
#pragma unroll 1
    for (int k0 = 0; k0 < 128; k0 += 32)
        gemm_chunk128(g_t[0], nullptr, 32, W2_in, k0, m0, 0.5f, sA, sW, acc2, tid);
#pragma unroll 1
    for (int k0 = 0; k0 < 64; k0 += 32)
        gemm_chunk128(x, nullptr, 16, Wr, k0, m0, 1.f, sA, sW, acc2, tid);

    const int rg = (tid >> 4) * 8;
    const int cg = (tid & 15) * 8;
#pragma unroll
    for (int i = 0; i < 8; i++) {
        int gr = m0 + rg + i;
        if (gr < N_NODES) {
            float o[8];
#pragma unroll
            for (int jp = 0; jp < 4; jp++) {
                float lo, hi;
                unpack2(acc2[i][jp], lo, hi);
                int c0 = cg + 2 * jp;
                o[2 * jp]     = lo + 0.5f * (b2_out[c0] + b2_in[c0]) + br[c0];
                o[2 * jp + 1] = hi + 0.5f * (b2_out[c0 + 1] + b2_in[c0 + 1]) + br[c0 + 1];
            }
            *(float4*)&out[(size_t)gr * EMB + cg]     = *(float4*)&o[0];
            *(float4*)&out[(size_t)gr * EMB + cg + 4] = *(float4*)&o[4];
        }
    }
}

// ---------------------------------------------------------------------------
// launch
// ---------------------------------------------------------------------------
extern "C" void kernel_launch(void* const* d_in, const int* in_sizes, int n_in,
                              void* d_out, int out_size)
{
    const float* x      = (const float*)d_in[0];
    const int*   ei     = (const int*)d_in[1];
    const float* ea     = (const float*)d_in[2];
    const float* We_in  = (const float*)d_in[3];
    const float* be_in  = (const float*)d_in[4];
    const float* W1_in  = (const float*)d_in[5];
    const float* b1_in  = (const float*)d_in[6];
    const float* W2_in  = (const float*)d_in[7];
    const float* b2_in  = (const float*)d_in[8];
    const float* We_out = (const float*)d_in[9];
    const float* be_out = (const float*)d_in[10];
    const float* W1_out = (const float*)d_in[11];
    const float* b1_out = (const float*)d_in[12];
    const float* W2_out = (const float*)d_in[13];
    const float* b2_out = (const float*)d_in[14];
    const float* Wr     = (const float*)d_in[15];
    const float* br     = (const float*)d_in[16];
    float* out = (float*)d_out;

    // ---- CSR build ----
    zero_deg_kernel<<<(N_NODES + 255) / 256, 256>>>();
    count_kernel<<<(N_EDGES + 255) / 256, 256>>>(ei);
    scan1_kernel<<<dim3(NBLK, 2), SCAN_BLK>>>();
    scan2_kernel<<<dim3(1, 2), 256>>>();
    scan3_kernel<<<dim3(NBLK, 2), SCAN_BLK>>>();
    fill_kernel<<<(N_EDGES + 255) / 256, 256>>>(ei);

    // ---- aggregation (atomic-free, f32x2, pipelined) ----
    agg_kernel<<<dim3(296, 2), 256>>>(
        (const float2*)x, ea,
        (const float2*)We_in,  (const float2*)be_in,
        (const float2*)We_out, (const float2*)be_out);

    // ---- node MLPs (f32x2) ----
    dim3 ngrid((N_NODES + 127) / 128, 2);
    n1_kernel<<<ngrid, 256>>>(x, W1_in, b1_in, W1_out, b1_out);

    n2_kernel<<<(N_NODES + 127) / 128, 256>>>(
        x, W2_in, b2_in, W2_out, b2_out, Wr, br, out);
}